// round 8
// baseline (speedup 1.0000x reference)
#include <cuda_runtime.h>

#define MAX_GRID 4096
__device__ float g_partial_ce[MAX_GRID];
__device__ float g_partial_rl[MAX_GRID];
__device__ unsigned int g_ticket = 0;

__device__ __forceinline__ float smooth_l1(float d) {
    float ad = fabsf(d);
    return (ad < 1.0f) ? 0.5f * d * d : ad - 0.5f;
}

__device__ __forceinline__ void accum_ce(int l, float cx, float cy, float& ce_sum)
{
    float m   = fmaxf(cx, cy);
    float d   = fabsf(cx - cy);
    float lse = m + __logf(1.0f + __expf(-d));
    float logit = (l == 1) ? cy : cx;
    float sel   = (l <= 1) ? 1.0f : 0.0f;
    ce_sum = fmaf(sel, lse - logit, ce_sum);
}

__device__ __forceinline__ void accum_rl(int l, int idx,
                                         const float4* __restrict__ rout,
                                         const float4* __restrict__ regt,
                                         float& rl_sum)
{
    if (l == 1) {
        float4 r = __ldg(rout + idx);
        float4 t = __ldg(regt + idx);
        float s = smooth_l1(r.x - t.x)
                + smooth_l1(r.y - t.y)
                + smooth_l1(r.z - t.z)
                + smooth_l1(r.w - t.w);
        rl_sum = fmaf(0.25f, s, rl_sum);
    }
}

// Each thread handles 4 consecutive anchors: int4 label + 2x float4 cout,
// conditional float4 rout/regt per positive anchor. Single pass, no loop.
__global__ void __launch_bounds__(256)
mbl_fused_kernel(const float4* __restrict__ cout4,   // 2 anchors per float4
                 const float4* __restrict__ rout,
                 const int4*   __restrict__ cls4,    // 4 labels
                 const float4* __restrict__ regt,
                 float* __restrict__ out,
                 int nq)                               // number of 4-anchor groups
{
    float ce_sum = 0.0f;
    float rl_sum = 0.0f;

    int q = blockIdx.x * blockDim.x + threadIdx.x;
    if (q < nq) {
        int4   l4 = __ldg(cls4 + q);
        float4 c0 = __ldg(cout4 + 2 * q);
        float4 c1 = __ldg(cout4 + 2 * q + 1);

        accum_ce(l4.x, c0.x, c0.y, ce_sum);
        accum_ce(l4.y, c0.z, c0.w, ce_sum);
        accum_ce(l4.z, c1.x, c1.y, ce_sum);
        accum_ce(l4.w, c1.z, c1.w, ce_sum);

        int base = 4 * q;
        accum_rl(l4.x, base + 0, rout, regt, rl_sum);
        accum_rl(l4.y, base + 1, rout, regt, rl_sum);
        accum_rl(l4.z, base + 2, rout, regt, rl_sum);
        accum_rl(l4.w, base + 3, rout, regt, rl_sum);
    }

    // intra-block reduction
    #pragma unroll
    for (int off = 16; off > 0; off >>= 1) {
        ce_sum += __shfl_down_sync(0xFFFFFFFF, ce_sum, off);
        rl_sum += __shfl_down_sync(0xFFFFFFFF, rl_sum, off);
    }

    __shared__ float s_ce[8];
    __shared__ float s_rl[8];
    __shared__ bool s_last;
    int lane = threadIdx.x & 31;
    int wid  = threadIdx.x >> 5;
    if (lane == 0) { s_ce[wid] = ce_sum; s_rl[wid] = rl_sum; }
    __syncthreads();

    if (threadIdx.x == 0) {
        float tce = 0.0f, trl = 0.0f;
        #pragma unroll
        for (int w = 0; w < 8; w++) { tce += s_ce[w]; trl += s_rl[w]; }
        g_partial_ce[blockIdx.x] = tce;
        g_partial_rl[blockIdx.x] = trl;
        __threadfence();
        unsigned int t = atomicAdd(&g_ticket, 1u);
        s_last = (t == gridDim.x - 1);
    }
    __syncthreads();

    if (s_last) {
        float ce = 0.0f, rl = 0.0f;
        for (int i = threadIdx.x; i < gridDim.x; i += 256) {
            ce += g_partial_ce[i];
            rl += g_partial_rl[i];
        }
        #pragma unroll
        for (int off = 16; off > 0; off >>= 1) {
            ce += __shfl_down_sync(0xFFFFFFFF, ce, off);
            rl += __shfl_down_sync(0xFFFFFFFF, rl, off);
        }
        if (lane == 0) { s_ce[wid] = ce; s_rl[wid] = rl; }
        __syncthreads();
        if (threadIdx.x == 0) {
            float tce = 0.0f, trl = 0.0f;
            #pragma unroll
            for (int w = 0; w < 8; w++) { tce += s_ce[w]; trl += s_rl[w]; }
            float closs = tce * (1.0f / 64.0f);
            float rloss = trl * (1.0f / 16.0f);
            out[0] = closs;
            out[1] = rloss;
            out[2] = closs + 10.0f * rloss;
            g_ticket = 0;   // reset for next graph replay
        }
    }
}

extern "C" void kernel_launch(void* const* d_in, const int* in_sizes, int n_in,
                              void* d_out, int out_size)
{
    const float4* cout4 = (const float4*)d_in[0];
    const float4* rout  = (const float4*)d_in[1];
    const int4*   cls4  = (const int4*)d_in[2];
    const float4* regt  = (const float4*)d_in[3];
    float* out = (float*)d_out;

    int n = in_sizes[2];            // N = 2,000,000 (divisible by 4)
    int nq = n >> 2;                // 500,000 groups of 4
    const int BLOCK = 256;
    int grid = (nq + BLOCK - 1) / BLOCK;   // 1954 blocks
    if (grid > MAX_GRID) grid = MAX_GRID;  // (not hit for this N)

    mbl_fused_kernel<<<grid, BLOCK>>>(cout4, rout, cls4, regt, out, nq);
}

// round 9
// speedup vs baseline: 1.3146x; 1.3146x over previous
#include <cuda_runtime.h>

#define MAX_GRID 4096
__device__ float g_partial_ce[MAX_GRID];
__device__ float g_partial_rl[MAX_GRID];
__device__ unsigned int g_ticket = 0;

__device__ __forceinline__ float smooth_l1(float d) {
    float ad = fabsf(d);
    return (ad < 1.0f) ? 0.5f * d * d : ad - 0.5f;
}

__device__ __forceinline__ void accum_ce(int l, float cx, float cy, float& ce_sum)
{
    float m   = fmaxf(cx, cy);
    float d   = fabsf(cx - cy);
    float lse = m + __logf(1.0f + __expf(-d));
    float logit = (l == 1) ? cy : cx;
    float sel   = (l <= 1) ? 1.0f : 0.0f;
    ce_sum = fmaf(sel, lse - logit, ce_sum);
}

__device__ __forceinline__ void accum_rl(int l, int idx,
                                         const float4* __restrict__ rout,
                                         const float4* __restrict__ regt,
                                         float& rl_sum)
{
    if (l == 1) {
        float4 r = __ldg(rout + idx);
        float4 t = __ldg(regt + idx);
        float s = smooth_l1(r.x - t.x)
                + smooth_l1(r.y - t.y)
                + smooth_l1(r.z - t.z)
                + smooth_l1(r.w - t.w);
        rl_sum = fmaf(0.25f, s, rl_sum);
    }
}

// Persistent grid-stride kernel, one wave (148 SMs x 8 blocks), 2 anchors per
// iteration (int2 labels + float4 cout front-batched), conditional regression
// loads for positive anchors only.
__global__ void __launch_bounds__(256)
mbl_fused_kernel(const float4* __restrict__ cout2,   // 2 anchors per float4
                 const float4* __restrict__ rout,
                 const int2*   __restrict__ cls2,    // 2 labels per int2
                 const float4* __restrict__ regt,
                 float* __restrict__ out,
                 int n)                                // n = number of PAIRS
{
    float ce_sum = 0.0f;
    float rl_sum = 0.0f;

    const int stride = gridDim.x * blockDim.x;
    for (int i = blockIdx.x * blockDim.x + threadIdx.x; i < n; i += stride) {
        int2   l2 = __ldg(cls2 + i);
        float4 c  = __ldg(cout2 + i);

        accum_ce(l2.x, c.x, c.y, ce_sum);
        accum_ce(l2.y, c.z, c.w, ce_sum);

        accum_rl(l2.x, 2 * i,     rout, regt, rl_sum);
        accum_rl(l2.y, 2 * i + 1, rout, regt, rl_sum);
    }

    // intra-block reduction
    #pragma unroll
    for (int off = 16; off > 0; off >>= 1) {
        ce_sum += __shfl_down_sync(0xFFFFFFFF, ce_sum, off);
        rl_sum += __shfl_down_sync(0xFFFFFFFF, rl_sum, off);
    }

    __shared__ float s_ce[8];
    __shared__ float s_rl[8];
    __shared__ bool s_last;
    int lane = threadIdx.x & 31;
    int wid  = threadIdx.x >> 5;
    if (lane == 0) { s_ce[wid] = ce_sum; s_rl[wid] = rl_sum; }
    __syncthreads();

    if (threadIdx.x == 0) {
        float tce = 0.0f, trl = 0.0f;
        #pragma unroll
        for (int w = 0; w < 8; w++) { tce += s_ce[w]; trl += s_rl[w]; }
        g_partial_ce[blockIdx.x] = tce;
        g_partial_rl[blockIdx.x] = trl;
        __threadfence();
        unsigned int t = atomicAdd(&g_ticket, 1u);
        s_last = (t == gridDim.x - 1);
    }
    __syncthreads();

    if (s_last) {
        float ce = 0.0f, rl = 0.0f;
        for (int i = threadIdx.x; i < gridDim.x; i += 256) {
            ce += g_partial_ce[i];
            rl += g_partial_rl[i];
        }
        #pragma unroll
        for (int off = 16; off > 0; off >>= 1) {
            ce += __shfl_down_sync(0xFFFFFFFF, ce, off);
            rl += __shfl_down_sync(0xFFFFFFFF, rl, off);
        }
        if (lane == 0) { s_ce[wid] = ce; s_rl[wid] = rl; }
        __syncthreads();
        if (threadIdx.x == 0) {
            float tce = 0.0f, trl = 0.0f;
            #pragma unroll
            for (int w = 0; w < 8; w++) { tce += s_ce[w]; trl += s_rl[w]; }
            float closs = tce * (1.0f / 64.0f);
            float rloss = trl * (1.0f / 16.0f);
            out[0] = closs;
            out[1] = rloss;
            out[2] = closs + 10.0f * rloss;
            g_ticket = 0;   // reset for next graph replay
        }
    }
}

extern "C" void kernel_launch(void* const* d_in, const int* in_sizes, int n_in,
                              void* d_out, int out_size)
{
    const float4* cout2 = (const float4*)d_in[0];
    const float4* rout  = (const float4*)d_in[1];
    const int2*   cls2  = (const int2*)d_in[2];
    const float4* regt  = (const float4*)d_in[3];
    float* out = (float*)d_out;

    int n_elems = in_sizes[2];     // N = 2,000,000 (even)
    int n_pairs = n_elems >> 1;
    const int BLOCK = 256;
    int grid = 148 * 8;            // one full wave
    if (grid > MAX_GRID) grid = MAX_GRID;

    mbl_fused_kernel<<<grid, BLOCK>>>(cout2, rout, cls2, regt, out, n_pairs);
}